// round 6
// baseline (speedup 1.0000x reference)
#include <cuda_runtime.h>
#include <cstdint>

#define T_SEQ 512
#define H 32
#define MAXB 4096

typedef unsigned long long u64;

// scratch: xin[b][t][i] = x[b][t]@W_ih1^T + (b_ih1 + b_hh1); +8 rows pad so the
// prefetch queue can read past the end unclamped (values never consumed).
__device__ float g_xin[((size_t)MAXB * T_SEQ + 8) * H];

__device__ __forceinline__ u64 fma2(u64 a, u64 b, u64 c) {
    u64 d;
    asm("fma.rn.f32x2 %0, %1, %2, %3;" : "=l"(d) : "l"(a), "l"(b), "l"(c));
    return d;
}
__device__ __forceinline__ u64 add2(u64 a, u64 b) {
    u64 d;
    asm("add.rn.f32x2 %0, %1, %2;" : "=l"(d) : "l"(a), "l"(b));
    return d;
}
__device__ __forceinline__ u64 pack2(float lo, float hi) {
    u64 d;
    asm("mov.b64 %0, {%1, %2};" : "=l"(d) : "f"(lo), "f"(hi));
    return d;
}
__device__ __forceinline__ float lo_hi_sum(u64 a) {
    unsigned lo, hi;
    asm("mov.b64 {%0,%1}, %2;" : "=r"(lo), "=r"(hi) : "l"(a));
    return __uint_as_float(lo) + __uint_as_float(hi);
}
// tanh(x) = 1 - 2/(exp(2x)+1); exp overflow -> inf -> 1. abs err ~1e-7.
__device__ __forceinline__ float tanh_fast(float x) {
    float e = __expf(2.0f * x);
    return 1.0f - __fdividef(2.0f, e + 1.0f);
}

// ============================================================================
// K1: xin precompute. lane = output i. W staged via padded shared; x broadcast
// via uniform LDS. 64 rows/warp, rows processed in PAIRS (4 indep fma chains).
// ============================================================================
__global__ __launch_bounds__(128)
void xin_kernel(const float* __restrict__ x,
                const float* __restrict__ W_ih1,
                const float* __restrict__ b_ih1,
                const float* __restrict__ b_hh1)
{
    const int tid  = threadIdx.x;
    const int lane = tid & 31;
    const int wid  = tid >> 5;

    __shared__ __align__(16) float sw[32][36];          // padded W rows
    __shared__ __align__(16) float sx[4][2][8 * H];     // per-warp dbl-buffered x tile

    #pragma unroll
    for (int idx = tid; idx < H * H; idx += 128) sw[idx >> 5][idx & 31] = W_ih1[idx];
    __syncthreads();

    u64 w[16];
    {
        const u64* wr = (const u64*)&sw[lane][0];
        #pragma unroll
        for (int k = 0; k < 16; k++) w[k] = wr[k];
    }
    const u64 biasp = pack2(b_ih1[lane] + b_hh1[lane], 0.0f);

    const long long base = ((long long)blockIdx.x * 4 + wid) * 64;
    const float* xb = x + base * H;
    float* ob = g_xin + base * H;

    float4 p0 = *(const float4*)(xb + lane * 4);
    float4 p1 = *(const float4*)(xb + 128 + lane * 4);

    #pragma unroll
    for (int g = 0; g < 8; g++) {
        const int buf = g & 1;
        *(float4*)&sx[wid][buf][lane * 4]       = p0;
        *(float4*)&sx[wid][buf][128 + lane * 4] = p1;
        if (g < 7) {
            p0 = *(const float4*)(xb + (g + 1) * 256 + lane * 4);
            p1 = *(const float4*)(xb + (g + 1) * 256 + 128 + lane * 4);
        }
        __syncwarp();

        #pragma unroll
        for (int rr = 0; rr < 8; rr += 2) {
            const ulonglong2* xv0 = (const ulonglong2*)&sx[wid][buf][rr * H];
            const ulonglong2* xv1 = (const ulonglong2*)&sx[wid][buf][(rr + 1) * H];
            u64 a0 = biasp, a1 = 0ull, b0 = biasp, b1 = 0ull;
            #pragma unroll
            for (int m = 0; m < 8; m++) {
                ulonglong2 v0 = xv0[m];
                ulonglong2 v1 = xv1[m];
                a0 = fma2(v0.x, w[2 * m],     a0);
                a1 = fma2(v0.y, w[2 * m + 1], a1);
                b0 = fma2(v1.x, w[2 * m],     b0);
                b1 = fma2(v1.y, w[2 * m + 1], b1);
            }
            ob[(g * 8 + rr)     * H + lane] = lo_hi_sum(add2(a0, a1));
            ob[(g * 8 + rr + 1) * H + lane] = lo_hi_sum(add2(b0, b1));
        }
    }
}

// ============================================================================
// K2: layer-pipelined recurrence, 2 batch streams/warp, SINGLE acc chain per
// matvec, xin/bias folded into acc init. __launch_bounds__(32,13) for occupancy.
//   h1_{k+1} = tanh(W_hh1 h1_k + xin_{k+1})
//   h2_k     = tanh(W_ih2 h1_k + W_hh2 h2_{k-1} + b2)
// ============================================================================
__global__ __launch_bounds__(32, 13)
void rnn_rec_kernel(const float* __restrict__ W_hh1,
                    const float* __restrict__ W_ih2,
                    const float* __restrict__ W_hh2,
                    const float* __restrict__ b_ih2,
                    const float* __restrict__ b_hh2,
                    const float* __restrict__ W_fc,
                    const float* __restrict__ b_fc,
                    float* __restrict__ out, int Bn)
{
    const int lane = threadIdx.x & 31;
    const int b0 = blockIdx.x * 2;
    if (b0 >= Bn) return;
    const int b1 = (b0 + 1 < Bn) ? (b0 + 1) : b0;

    // [pingpong][ A.h1 | A.h2 | B.h1 | B.h2 ]
    __shared__ __align__(16) float s[2][4 * H];

    u64 whh1[16], wih2[16], whh2[16];
    {
        const u64* p1 = (const u64*)(W_hh1 + lane * H);
        const u64* p2 = (const u64*)(W_ih2 + lane * H);
        const u64* p3 = (const u64*)(W_hh2 + lane * H);
        #pragma unroll
        for (int k = 0; k < 16; k++) { whh1[k] = p1[k]; wih2[k] = p2[k]; whh2[k] = p3[k]; }
    }
    const u64 bias2p = pack2(b_ih2[lane] + b_hh2[lane], 0.0f);

    const float* xA = g_xin + (size_t)b0 * T_SEQ * H + lane;
    const float* xB = g_xin + (size_t)b1 * T_SEQ * H + lane;

    // prologue: h1_0 = tanh(xin_0), h2_{-1}=0, published to buffer 1
    s[1][lane]          = tanh_fast(xA[0]);
    s[1][H + lane]      = 0.0f;
    s[1][2 * H + lane]  = tanh_fast(xB[0]);
    s[1][3 * H + lane]  = 0.0f;
    __syncwarp();

    // xin queues, depth 4 (consume index k+1 at step k); reads past end hit pad
    float qA0 = xA[1 * H], qA1 = xA[2 * H], qA2 = xA[3 * H], qA3 = xA[4 * H];
    float qB0 = xB[1 * H], qB1 = xB[2 * H], qB2 = xB[3 * H], qB3 = xB[4 * H];

    float h2A = 0.0f, h2B = 0.0f;

    #pragma unroll 4
    for (int k = 0; k < T_SEQ; ++k) {
        const int p = k & 1;
        const ulonglong2* hp = (const ulonglong2*)&s[p ^ 1][0];

        // acc inits carry xin (layer1) and bias2 (layer2)
        u64 aA = pack2(qA0, 0.0f), aB = pack2(qB0, 0.0f);
        u64 cA = bias2p,           cB = bias2p;
        u64 dA = 0ull,             dB = 0ull;

        #pragma unroll
        for (int m = 0; m < 8; m++) {
            ulonglong2 vA = hp[m];          // A.h1_k
            ulonglong2 vB = hp[16 + m];     // B.h1_k
            aA = fma2(vA.x, whh1[2 * m],     aA);
            aA = fma2(vA.y, whh1[2 * m + 1], aA);
            cA = fma2(vA.x, wih2[2 * m],     cA);
            cA = fma2(vA.y, wih2[2 * m + 1], cA);
            aB = fma2(vB.x, whh1[2 * m],     aB);
            aB = fma2(vB.y, whh1[2 * m + 1], aB);
            cB = fma2(vB.x, wih2[2 * m],     cB);
            cB = fma2(vB.y, wih2[2 * m + 1], cB);
        }
        #pragma unroll
        for (int m = 0; m < 8; m++) {
            ulonglong2 vA = hp[8 + m];      // A.h2_{k-1}
            ulonglong2 vB = hp[24 + m];     // B.h2_{k-1}
            dA = fma2(vA.x, whh2[2 * m],     dA);
            dA = fma2(vA.y, whh2[2 * m + 1], dA);
            dB = fma2(vB.x, whh2[2 * m],     dB);
            dB = fma2(vB.y, whh2[2 * m + 1], dB);
        }

        const float h1nA = tanh_fast(lo_hi_sum(aA));
        const float h2nA = tanh_fast(lo_hi_sum(add2(cA, dA)));
        const float h1nB = tanh_fast(lo_hi_sum(aB));
        const float h2nB = tanh_fast(lo_hi_sum(add2(cB, dB)));

        // rotate queues + refill at k+5 (no clamp; pad absorbs overrun)
        qA0 = qA1; qA1 = qA2; qA2 = qA3;
        qB0 = qB1; qB1 = qB2; qB2 = qB3;
        qA3 = xA[(size_t)(k + 5) * H];
        qB3 = xB[(size_t)(k + 5) * H];

        s[p][lane]         = h1nA;
        s[p][H + lane]     = h2nA;
        s[p][2 * H + lane] = h1nB;
        s[p][3 * H + lane] = h2nB;
        __syncwarp();

        h2A = h2nA; h2B = h2nB;
    }

    float vA = h2A * W_fc[lane];
    float vB = h2B * W_fc[lane];
    #pragma unroll
    for (int o = 16; o; o >>= 1) {
        vA += __shfl_xor_sync(0xFFFFFFFFu, vA, o);
        vB += __shfl_xor_sync(0xFFFFFFFFu, vB, o);
    }
    if (lane == 0) {
        out[b0] = vA + b_fc[0];
        if (b1 != b0) out[b1] = vB + b_fc[0];
    }
}

extern "C" void kernel_launch(void* const* d_in, const int* in_sizes, int n_in,
                              void* d_out, int out_size)
{
    const float* x     = (const float*)d_in[0];
    const float* W_ih1 = (const float*)d_in[1];
    const float* W_hh1 = (const float*)d_in[2];
    const float* b_ih1 = (const float*)d_in[3];
    const float* b_hh1 = (const float*)d_in[4];
    const float* W_ih2 = (const float*)d_in[5];
    const float* W_hh2 = (const float*)d_in[6];
    const float* b_ih2 = (const float*)d_in[7];
    const float* b_hh2 = (const float*)d_in[8];
    const float* W_fc  = (const float*)d_in[9];
    const float* b_fc  = (const float*)d_in[10];
    float* out = (float*)d_out;

    const int Bn = in_sizes[0] / (T_SEQ * H);

    const int rows = Bn * T_SEQ;
    xin_kernel<<<rows / 256, 128>>>(x, W_ih1, b_ih1, b_hh1);

    rnn_rec_kernel<<<(Bn + 1) / 2, 32>>>(
        W_hh1, W_ih2, W_hh2, b_ih2, b_hh2, W_fc, b_fc, out, Bn);
}

// round 7
// speedup vs baseline: 1.0495x; 1.0495x over previous
#include <cuda_runtime.h>
#include <cstdint>

#define T_SEQ 512
#define H 32
#define MAXB 4096

typedef unsigned long long u64;

// scratch: xin[b][t][i] = x[b][t]@W_ih1^T + (b_ih1 + b_hh1); +8 rows pad so the
// prefetch queue can read past the end unclamped.
__device__ float g_xin[((size_t)MAXB * T_SEQ + 8) * H];

__device__ __forceinline__ u64 fma2(u64 a, u64 b, u64 c) {
    u64 d;
    asm("fma.rn.f32x2 %0, %1, %2, %3;" : "=l"(d) : "l"(a), "l"(b), "l"(c));
    return d;
}
__device__ __forceinline__ u64 add2(u64 a, u64 b) {
    u64 d;
    asm("add.rn.f32x2 %0, %1, %2;" : "=l"(d) : "l"(a), "l"(b));
    return d;
}
__device__ __forceinline__ u64 pack2(float lo, float hi) {
    u64 d;
    asm("mov.b64 %0, {%1, %2};" : "=l"(d) : "f"(lo), "f"(hi));
    return d;
}
__device__ __forceinline__ float lo_hi_sum(u64 a) {
    unsigned lo, hi;
    asm("mov.b64 {%0,%1}, %2;" : "=r"(lo), "=r"(hi) : "l"(a));
    return __uint_as_float(lo) + __uint_as_float(hi);
}
// single-instruction MUFU tanh (sm_75+), ~1e-5 accuracy
__device__ __forceinline__ float tanh_mufu(float x) {
    float y;
    asm("tanh.approx.f32 %0, %1;" : "=f"(y) : "f"(x));
    return y;
}
// accurate tanh for K1-free prologue use (cheap, off hot path)
__device__ __forceinline__ float tanh_fast(float x) {
    float e = __expf(2.0f * x);
    return 1.0f - __fdividef(2.0f, e + 1.0f);
}

// ============================================================================
// K1: xin precompute (unchanged; ~DRAM-bound). lane = output i, W via padded
// shared, x broadcast via uniform LDS, 64 rows/warp in pairs.
// ============================================================================
__global__ __launch_bounds__(128)
void xin_kernel(const float* __restrict__ x,
                const float* __restrict__ W_ih1,
                const float* __restrict__ b_ih1,
                const float* __restrict__ b_hh1)
{
    const int tid  = threadIdx.x;
    const int lane = tid & 31;
    const int wid  = tid >> 5;

    __shared__ __align__(16) float sw[32][36];
    __shared__ __align__(16) float sx[4][2][8 * H];

    #pragma unroll
    for (int idx = tid; idx < H * H; idx += 128) sw[idx >> 5][idx & 31] = W_ih1[idx];
    __syncthreads();

    u64 w[16];
    {
        const u64* wr = (const u64*)&sw[lane][0];
        #pragma unroll
        for (int k = 0; k < 16; k++) w[k] = wr[k];
    }
    const u64 biasp = pack2(b_ih1[lane] + b_hh1[lane], 0.0f);

    const long long base = ((long long)blockIdx.x * 4 + wid) * 64;
    const float* xb = x + base * H;
    float* ob = g_xin + base * H;

    float4 p0 = *(const float4*)(xb + lane * 4);
    float4 p1 = *(const float4*)(xb + 128 + lane * 4);

    #pragma unroll
    for (int g = 0; g < 8; g++) {
        const int buf = g & 1;
        *(float4*)&sx[wid][buf][lane * 4]       = p0;
        *(float4*)&sx[wid][buf][128 + lane * 4] = p1;
        if (g < 7) {
            p0 = *(const float4*)(xb + (g + 1) * 256 + lane * 4);
            p1 = *(const float4*)(xb + (g + 1) * 256 + 128 + lane * 4);
        }
        __syncwarp();

        #pragma unroll
        for (int rr = 0; rr < 8; rr += 2) {
            const ulonglong2* xv0 = (const ulonglong2*)&sx[wid][buf][rr * H];
            const ulonglong2* xv1 = (const ulonglong2*)&sx[wid][buf][(rr + 1) * H];
            u64 a0 = biasp, a1 = 0ull, b0 = biasp, b1 = 0ull;
            #pragma unroll
            for (int m = 0; m < 8; m++) {
                ulonglong2 v0 = xv0[m];
                ulonglong2 v1 = xv1[m];
                a0 = fma2(v0.x, w[2 * m],     a0);
                a1 = fma2(v0.y, w[2 * m + 1], a1);
                b0 = fma2(v1.x, w[2 * m],     b0);
                b1 = fma2(v1.y, w[2 * m + 1], b1);
            }
            ob[(g * 8 + rr)     * H + lane] = lo_hi_sum(add2(a0, a1));
            ob[(g * 8 + rr + 1) * H + lane] = lo_hi_sum(add2(b0, b1));
        }
    }
}

// ============================================================================
// K2: layer-pipelined recurrence, 2 batch streams/warp, HALF-J work split:
// lane L covers j in [16*(L>>4), 16*(L>>4)+16) for output units (L&15) and
// (L&15)+16; half-sums combined via shfl_xor(16). Halves LDS bytes per lane.
//   h1_{k+1} = tanh(W_hh1 h1_k + xin_{k+1})
//   h2_k     = tanh(W_ih2 h1_k + W_hh2 h2_{k-1} + b2)
// ============================================================================
__global__ __launch_bounds__(32, 13)
void rnn_rec_kernel(const float* __restrict__ W_hh1,
                    const float* __restrict__ W_ih2,
                    const float* __restrict__ W_hh2,
                    const float* __restrict__ b_ih2,
                    const float* __restrict__ b_hh2,
                    const float* __restrict__ W_fc,
                    const float* __restrict__ b_fc,
                    float* __restrict__ out, int Bn)
{
    const int lane = threadIdx.x & 31;
    const int jh   = lane >> 4;        // which j-half this lane reads
    const int u0   = lane & 15;        // unit pair (u0, u0+16)
    const int b0 = blockIdx.x * 2;
    if (b0 >= Bn) return;
    const int b1 = (b0 + 1 < Bn) ? (b0 + 1) : b0;

    // [pingpong][ A.h1 | A.h2 | B.h1 | B.h2 ]
    __shared__ __align__(16) float s[2][4 * H];

    // per-lane weight half-rows: rows u0 and u0+16, columns [16*jh, 16*jh+16)
    u64 w1_0[8], w1_1[8], w2_0[8], w2_1[8], w3_0[8], w3_1[8];
    {
        const int off = jh * 16;
        const u64* p;
        p = (const u64*)(W_hh1 + u0 * H + off);
        #pragma unroll
        for (int k = 0; k < 8; k++) w1_0[k] = p[k];
        p = (const u64*)(W_hh1 + (u0 + 16) * H + off);
        #pragma unroll
        for (int k = 0; k < 8; k++) w1_1[k] = p[k];
        p = (const u64*)(W_ih2 + u0 * H + off);
        #pragma unroll
        for (int k = 0; k < 8; k++) w2_0[k] = p[k];
        p = (const u64*)(W_ih2 + (u0 + 16) * H + off);
        #pragma unroll
        for (int k = 0; k < 8; k++) w2_1[k] = p[k];
        p = (const u64*)(W_hh2 + u0 * H + off);
        #pragma unroll
        for (int k = 0; k < 8; k++) w3_0[k] = p[k];
        p = (const u64*)(W_hh2 + (u0 + 16) * H + off);
        #pragma unroll
        for (int k = 0; k < 8; k++) w3_1[k] = p[k];
    }
    const float bias2 = b_ih2[lane] + b_hh2[lane];   // per-unit (unit == lane)

    const float* xA = g_xin + (size_t)b0 * T_SEQ * H + lane;
    const float* xB = g_xin + (size_t)b1 * T_SEQ * H + lane;

    // prologue: h1_0 = tanh(xin_0), h2_{-1}=0, published to buffer 1
    s[1][lane]          = tanh_fast(xA[0]);
    s[1][H + lane]      = 0.0f;
    s[1][2 * H + lane]  = tanh_fast(xB[0]);
    s[1][3 * H + lane]  = 0.0f;
    __syncwarp();

    // xin queues, depth 4 (consume index k+1 at step k); pad absorbs overrun
    float qA0 = xA[1 * H], qA1 = xA[2 * H], qA2 = xA[3 * H], qA3 = xA[4 * H];
    float qB0 = xB[1 * H], qB1 = xB[2 * H], qB2 = xB[3 * H], qB3 = xB[4 * H];

    float h2A = 0.0f, h2B = 0.0f;

    #pragma unroll 4
    for (int k = 0; k < T_SEQ; ++k) {
        const int p = k & 1;
        const float* sq = &s[p ^ 1][jh * 16];
        const ulonglong2* h1Av = (const ulonglong2*)(sq);
        const ulonglong2* h2Av = (const ulonglong2*)(sq + H);
        const ulonglong2* h1Bv = (const ulonglong2*)(sq + 2 * H);
        const ulonglong2* h2Bv = (const ulonglong2*)(sq + 3 * H);

        u64 aA0 = 0ull, aA1 = 0ull, cA0 = 0ull, cA1 = 0ull;
        u64 aB0 = 0ull, aB1 = 0ull, cB0 = 0ull, cB1 = 0ull;

        #pragma unroll
        for (int m = 0; m < 4; m++) {
            ulonglong2 vA = h1Av[m];
            ulonglong2 vB = h1Bv[m];
            aA0 = fma2(vA.x, w1_0[2 * m],     aA0);
            aA0 = fma2(vA.y, w1_0[2 * m + 1], aA0);
            aA1 = fma2(vA.x, w1_1[2 * m],     aA1);
            aA1 = fma2(vA.y, w1_1[2 * m + 1], aA1);
            cA0 = fma2(vA.x, w2_0[2 * m],     cA0);
            cA0 = fma2(vA.y, w2_0[2 * m + 1], cA0);
            cA1 = fma2(vA.x, w2_1[2 * m],     cA1);
            cA1 = fma2(vA.y, w2_1[2 * m + 1], cA1);
            aB0 = fma2(vB.x, w1_0[2 * m],     aB0);
            aB0 = fma2(vB.y, w1_0[2 * m + 1], aB0);
            aB1 = fma2(vB.x, w1_1[2 * m],     aB1);
            aB1 = fma2(vB.y, w1_1[2 * m + 1], aB1);
            cB0 = fma2(vB.x, w2_0[2 * m],     cB0);
            cB0 = fma2(vB.y, w2_0[2 * m + 1], cB0);
            cB1 = fma2(vB.x, w2_1[2 * m],     cB1);
            cB1 = fma2(vB.y, w2_1[2 * m + 1], cB1);
        }
        #pragma unroll
        for (int m = 0; m < 4; m++) {
            ulonglong2 vA = h2Av[m];
            ulonglong2 vB = h2Bv[m];
            cA0 = fma2(vA.x, w3_0[2 * m],     cA0);
            cA0 = fma2(vA.y, w3_0[2 * m + 1], cA0);
            cA1 = fma2(vA.x, w3_1[2 * m],     cA1);
            cA1 = fma2(vA.y, w3_1[2 * m + 1], cA1);
            cB0 = fma2(vB.x, w3_0[2 * m],     cB0);
            cB0 = fma2(vB.y, w3_0[2 * m + 1], cB0);
            cB1 = fma2(vB.x, w3_1[2 * m],     cB1);
            cB1 = fma2(vB.y, w3_1[2 * m + 1], cB1);
        }

        // combine half-sums across the jh partner (lane ^ 16)
        float sa0 = lo_hi_sum(aA0), sa1 = lo_hi_sum(aA1);
        float sc0 = lo_hi_sum(cA0), sc1 = lo_hi_sum(cA1);
        float sb0 = lo_hi_sum(aB0), sb1 = lo_hi_sum(aB1);
        float sd0 = lo_hi_sum(cB0), sd1 = lo_hi_sum(cB1);

        float fa0 = sa0 + __shfl_xor_sync(0xFFFFFFFFu, sa0, 16);
        float fa1 = sa1 + __shfl_xor_sync(0xFFFFFFFFu, sa1, 16);
        float fc0 = sc0 + __shfl_xor_sync(0xFFFFFFFFu, sc0, 16);
        float fc1 = sc1 + __shfl_xor_sync(0xFFFFFFFFu, sc1, 16);
        float fb0 = sb0 + __shfl_xor_sync(0xFFFFFFFFu, sb0, 16);
        float fb1 = sb1 + __shfl_xor_sync(0xFFFFFFFFu, sb1, 16);
        float fd0 = sd0 + __shfl_xor_sync(0xFFFFFFFFu, sd0, 16);
        float fd1 = sd1 + __shfl_xor_sync(0xFFFFFFFFu, sd1, 16);

        // lane keeps its own unit (unit == lane): u0 half -> f*0, u1 half -> f*1
        const float h1nA = tanh_mufu((jh ? fa1 : fa0) + qA0);
        const float h2nA = tanh_mufu((jh ? fc1 : fc0) + bias2);
        const float h1nB = tanh_mufu((jh ? fb1 : fb0) + qB0);
        const float h2nB = tanh_mufu((jh ? fd1 : fd0) + bias2);

        // rotate queues + refill at k+5
        qA0 = qA1; qA1 = qA2; qA2 = qA3;
        qB0 = qB1; qB1 = qB2; qB2 = qB3;
        qA3 = xA[(size_t)(k + 5) * H];
        qB3 = xB[(size_t)(k + 5) * H];

        s[p][lane]         = h1nA;
        s[p][H + lane]     = h2nA;
        s[p][2 * H + lane] = h1nB;
        s[p][3 * H + lane] = h2nB;
        __syncwarp();

        h2A = h2nA; h2B = h2nB;
    }

    float vA = h2A * W_fc[lane];
    float vB = h2B * W_fc[lane];
    #pragma unroll
    for (int o = 16; o; o >>= 1) {
        vA += __shfl_xor_sync(0xFFFFFFFFu, vA, o);
        vB += __shfl_xor_sync(0xFFFFFFFFu, vB, o);
    }
    if (lane == 0) {
        out[b0] = vA + b_fc[0];
        if (b1 != b0) out[b1] = vB + b_fc[0];
    }
}

extern "C" void kernel_launch(void* const* d_in, const int* in_sizes, int n_in,
                              void* d_out, int out_size)
{
    const float* x     = (const float*)d_in[0];
    const float* W_ih1 = (const float*)d_in[1];
    const float* W_hh1 = (const float*)d_in[2];
    const float* b_ih1 = (const float*)d_in[3];
    const float* b_hh1 = (const float*)d_in[4];
    const float* W_ih2 = (const float*)d_in[5];
    const float* W_hh2 = (const float*)d_in[6];
    const float* b_ih2 = (const float*)d_in[7];
    const float* b_hh2 = (const float*)d_in[8];
    const float* W_fc  = (const float*)d_in[9];
    const float* b_fc  = (const float*)d_in[10];
    float* out = (float*)d_out;

    const int Bn = in_sizes[0] / (T_SEQ * H);

    const int rows = Bn * T_SEQ;
    xin_kernel<<<rows / 256, 128>>>(x, W_ih1, b_ih1, b_hh1);

    rnn_rec_kernel<<<(Bn + 1) / 2, 32>>>(
        W_hh1, W_ih2, W_hh2, b_ih2, b_hh2, W_fc, b_fc, out, Bn);
}

// round 8
// speedup vs baseline: 1.1212x; 1.0683x over previous
#include <cuda_runtime.h>
#include <cstdint>

#define T_SEQ 512
#define H 32
#define MAXB 4096
#define GSTEP 16   // xin tile depth (steps per prefetch group)

typedef unsigned long long u64;

// scratch: xin[b][t][i]; +24 rows pad so tile prefetch may overrun past the
// final batch's end (values never consumed).
__device__ float g_xin[((size_t)MAXB * T_SEQ + 24) * H];

__device__ __forceinline__ u64 fma2(u64 a, u64 b, u64 c) {
    u64 d;
    asm("fma.rn.f32x2 %0, %1, %2, %3;" : "=l"(d) : "l"(a), "l"(b), "l"(c));
    return d;
}
__device__ __forceinline__ u64 add2(u64 a, u64 b) {
    u64 d;
    asm("add.rn.f32x2 %0, %1, %2;" : "=l"(d) : "l"(a), "l"(b));
    return d;
}
__device__ __forceinline__ u64 pack2(float lo, float hi) {
    u64 d;
    asm("mov.b64 %0, {%1, %2};" : "=l"(d) : "f"(lo), "f"(hi));
    return d;
}
__device__ __forceinline__ float lo_hi_sum(u64 a) {
    unsigned lo, hi;
    asm("mov.b64 {%0,%1}, %2;" : "=r"(lo), "=r"(hi) : "l"(a));
    return __uint_as_float(lo) + __uint_as_float(hi);
}
__device__ __forceinline__ float tanh_mufu(float x) {
    float y;
    asm("tanh.approx.f32 %0, %1;" : "=f"(y) : "f"(x));
    return y;
}
__device__ __forceinline__ float tanh_fast(float x) {
    float e = __expf(2.0f * x);
    return 1.0f - __fdividef(2.0f, e + 1.0f);
}

// ============================================================================
// K1: xin precompute (unchanged from round 7).
// ============================================================================
__global__ __launch_bounds__(128)
void xin_kernel(const float* __restrict__ x,
                const float* __restrict__ W_ih1,
                const float* __restrict__ b_ih1,
                const float* __restrict__ b_hh1)
{
    const int tid  = threadIdx.x;
    const int lane = tid & 31;
    const int wid  = tid >> 5;

    __shared__ __align__(16) float sw[32][36];
    __shared__ __align__(16) float sx[4][2][8 * H];

    #pragma unroll
    for (int idx = tid; idx < H * H; idx += 128) sw[idx >> 5][idx & 31] = W_ih1[idx];
    __syncthreads();

    u64 w[16];
    {
        const u64* wr = (const u64*)&sw[lane][0];
        #pragma unroll
        for (int k = 0; k < 16; k++) w[k] = wr[k];
    }
    const u64 biasp = pack2(b_ih1[lane] + b_hh1[lane], 0.0f);

    const long long base = ((long long)blockIdx.x * 4 + wid) * 64;
    const float* xb = x + base * H;
    float* ob = g_xin + base * H;

    float4 p0 = *(const float4*)(xb + lane * 4);
    float4 p1 = *(const float4*)(xb + 128 + lane * 4);

    #pragma unroll
    for (int g = 0; g < 8; g++) {
        const int buf = g & 1;
        *(float4*)&sx[wid][buf][lane * 4]       = p0;
        *(float4*)&sx[wid][buf][128 + lane * 4] = p1;
        if (g < 7) {
            p0 = *(const float4*)(xb + (g + 1) * 256 + lane * 4);
            p1 = *(const float4*)(xb + (g + 1) * 256 + 128 + lane * 4);
        }
        __syncwarp();

        #pragma unroll
        for (int rr = 0; rr < 8; rr += 2) {
            const ulonglong2* xv0 = (const ulonglong2*)&sx[wid][buf][rr * H];
            const ulonglong2* xv1 = (const ulonglong2*)&sx[wid][buf][(rr + 1) * H];
            u64 a0 = biasp, a1 = 0ull, b0 = biasp, b1 = 0ull;
            #pragma unroll
            for (int m = 0; m < 8; m++) {
                ulonglong2 v0 = xv0[m];
                ulonglong2 v1 = xv1[m];
                a0 = fma2(v0.x, w[2 * m],     a0);
                a1 = fma2(v0.y, w[2 * m + 1], a1);
                b0 = fma2(v1.x, w[2 * m],     b0);
                b1 = fma2(v1.y, w[2 * m + 1], b1);
            }
            ob[(g * 8 + rr)     * H + lane] = lo_hi_sum(add2(a0, a1));
            ob[(g * 8 + rr + 1) * H + lane] = lo_hi_sum(add2(b0, b1));
        }
    }
}

// ============================================================================
// K2: layer-pipelined recurrence, 2 streams/warp, half-j split (round 7) +
// DEEP xin prefetch: double-buffered smem tile of GSTEP=16 steps, burst-loaded
// (32 coalesced LDGs, MLP=32) one group ahead -> DRAM latency off the
// per-step critical path. Each lane stores/reads only its own slot (no sync
// needed for the tile).
// ============================================================================
__global__ __launch_bounds__(32, 13)
void rnn_rec_kernel(const float* __restrict__ W_hh1,
                    const float* __restrict__ W_ih2,
                    const float* __restrict__ W_hh2,
                    const float* __restrict__ b_ih2,
                    const float* __restrict__ b_hh2,
                    const float* __restrict__ W_fc,
                    const float* __restrict__ b_fc,
                    float* __restrict__ out, int Bn)
{
    const int lane = threadIdx.x & 31;
    const int jh   = lane >> 4;
    const int u0   = lane & 15;
    const int b0 = blockIdx.x * 2;
    if (b0 >= Bn) return;
    const int b1 = (b0 + 1 < Bn) ? (b0 + 1) : b0;

    __shared__ __align__(16) float s[2][4 * H];             // h ping-pong
    __shared__ float sx[2][2][GSTEP][32];                   // xin tile [buf][stream][d][lane]

    u64 w1_0[8], w1_1[8], w2_0[8], w2_1[8], w3_0[8], w3_1[8];
    {
        const int off = jh * 16;
        const u64* p;
        p = (const u64*)(W_hh1 + u0 * H + off);
        #pragma unroll
        for (int k = 0; k < 8; k++) w1_0[k] = p[k];
        p = (const u64*)(W_hh1 + (u0 + 16) * H + off);
        #pragma unroll
        for (int k = 0; k < 8; k++) w1_1[k] = p[k];
        p = (const u64*)(W_ih2 + u0 * H + off);
        #pragma unroll
        for (int k = 0; k < 8; k++) w2_0[k] = p[k];
        p = (const u64*)(W_ih2 + (u0 + 16) * H + off);
        #pragma unroll
        for (int k = 0; k < 8; k++) w2_1[k] = p[k];
        p = (const u64*)(W_hh2 + u0 * H + off);
        #pragma unroll
        for (int k = 0; k < 8; k++) w3_0[k] = p[k];
        p = (const u64*)(W_hh2 + (u0 + 16) * H + off);
        #pragma unroll
        for (int k = 0; k < 8; k++) w3_1[k] = p[k];
    }
    const float bias2 = b_ih2[lane] + b_hh2[lane];

    const float* xA = g_xin + (size_t)b0 * T_SEQ * H + lane;
    const float* xB = g_xin + (size_t)b1 * T_SEQ * H + lane;

    // prologue: h1_0 = tanh(xin_0), h2_{-1}=0, published to buffer 1
    s[1][lane]          = tanh_fast(xA[0]);
    s[1][H + lane]      = 0.0f;
    s[1][2 * H + lane]  = tanh_fast(xB[0]);
    s[1][3 * H + lane]  = 0.0f;
    __syncwarp();

    // preload tile group 0 (covers steps k=0..15, i.e. t=1..16)
    #pragma unroll
    for (int d = 0; d < GSTEP; d++) {
        float vA = xA[(size_t)(d + 1) * H];
        float vB = xB[(size_t)(d + 1) * H];
        sx[0][0][d][lane] = vA;
        sx[0][1][d][lane] = vB;
    }

    float h2A = 0.0f, h2B = 0.0f;

    for (int g = 0; g < T_SEQ / GSTEP; ++g) {
        const int buf = g & 1;

        // burst-prefetch next tile (steps (g+1)*16 .. +15 -> t = that +1).
        // Overrun past t=511 lands in the pad / next batch rows (never consumed).
        {
            const int nbuf = buf ^ 1;
            const size_t tb = (size_t)(g + 1) * GSTEP + 1;
            #pragma unroll
            for (int d = 0; d < GSTEP; d++) {
                float vA = xA[(tb + d) * H];
                float vB = xB[(tb + d) * H];
                sx[nbuf][0][d][lane] = vA;
                sx[nbuf][1][d][lane] = vB;
            }
        }

        #pragma unroll
        for (int kk = 0; kk < GSTEP; ++kk) {
            const int p = kk & 1;   // g*16 is even, so parity of k == parity of kk
            const float* sq = &s[p ^ 1][jh * 16];
            const ulonglong2* h1Av = (const ulonglong2*)(sq);
            const ulonglong2* h2Av = (const ulonglong2*)(sq + H);
            const ulonglong2* h1Bv = (const ulonglong2*)(sq + 2 * H);
            const ulonglong2* h2Bv = (const ulonglong2*)(sq + 3 * H);

            u64 aA0 = 0ull, aA1 = 0ull, cA0 = 0ull, cA1 = 0ull;
            u64 aB0 = 0ull, aB1 = 0ull, cB0 = 0ull, cB1 = 0ull;

            #pragma unroll
            for (int m = 0; m < 4; m++) {
                ulonglong2 vA = h1Av[m];
                ulonglong2 vB = h1Bv[m];
                aA0 = fma2(vA.x, w1_0[2 * m],     aA0);
                aA0 = fma2(vA.y, w1_0[2 * m + 1], aA0);
                aA1 = fma2(vA.x, w1_1[2 * m],     aA1);
                aA1 = fma2(vA.y, w1_1[2 * m + 1], aA1);
                cA0 = fma2(vA.x, w2_0[2 * m],     cA0);
                cA0 = fma2(vA.y, w2_0[2 * m + 1], cA0);
                cA1 = fma2(vA.x, w2_1[2 * m],     cA1);
                cA1 = fma2(vA.y, w2_1[2 * m + 1], cA1);
                aB0 = fma2(vB.x, w1_0[2 * m],     aB0);
                aB0 = fma2(vB.y, w1_0[2 * m + 1], aB0);
                aB1 = fma2(vB.x, w1_1[2 * m],     aB1);
                aB1 = fma2(vB.y, w1_1[2 * m + 1], aB1);
                cB0 = fma2(vB.x, w2_0[2 * m],     cB0);
                cB0 = fma2(vB.y, w2_0[2 * m + 1], cB0);
                cB1 = fma2(vB.x, w2_1[2 * m],     cB1);
                cB1 = fma2(vB.y, w2_1[2 * m + 1], cB1);
            }
            #pragma unroll
            for (int m = 0; m < 4; m++) {
                ulonglong2 vA = h2Av[m];
                ulonglong2 vB = h2Bv[m];
                cA0 = fma2(vA.x, w3_0[2 * m],     cA0);
                cA0 = fma2(vA.y, w3_0[2 * m + 1], cA0);
                cA1 = fma2(vA.x, w3_1[2 * m],     cA1);
                cA1 = fma2(vA.y, w3_1[2 * m + 1], cA1);
                cB0 = fma2(vB.x, w3_0[2 * m],     cB0);
                cB0 = fma2(vB.y, w3_0[2 * m + 1], cB0);
                cB1 = fma2(vB.x, w3_1[2 * m],     cB1);
                cB1 = fma2(vB.y, w3_1[2 * m + 1], cB1);
            }

            float sa0 = lo_hi_sum(aA0), sa1 = lo_hi_sum(aA1);
            float sc0 = lo_hi_sum(cA0), sc1 = lo_hi_sum(cA1);
            float sb0 = lo_hi_sum(aB0), sb1 = lo_hi_sum(aB1);
            float sd0 = lo_hi_sum(cB0), sd1 = lo_hi_sum(cB1);

            float fa0 = sa0 + __shfl_xor_sync(0xFFFFFFFFu, sa0, 16);
            float fa1 = sa1 + __shfl_xor_sync(0xFFFFFFFFu, sa1, 16);
            float fc0 = sc0 + __shfl_xor_sync(0xFFFFFFFFu, sc0, 16);
            float fc1 = sc1 + __shfl_xor_sync(0xFFFFFFFFu, sc1, 16);
            float fb0 = sb0 + __shfl_xor_sync(0xFFFFFFFFu, sb0, 16);
            float fb1 = sb1 + __shfl_xor_sync(0xFFFFFFFFu, sb1, 16);
            float fd0 = sd0 + __shfl_xor_sync(0xFFFFFFFFu, sd0, 16);
            float fd1 = sd1 + __shfl_xor_sync(0xFFFFFFFFu, sd1, 16);

            const float xinA = sx[buf][0][kk][lane];   // value for t = k+1
            const float xinB = sx[buf][1][kk][lane];

            const float h1nA = tanh_mufu((jh ? fa1 : fa0) + xinA);
            const float h2nA = tanh_mufu((jh ? fc1 : fc0) + bias2);
            const float h1nB = tanh_mufu((jh ? fb1 : fb0) + xinB);
            const float h2nB = tanh_mufu((jh ? fd1 : fd0) + bias2);

            s[p][lane]         = h1nA;
            s[p][H + lane]     = h2nA;
            s[p][2 * H + lane] = h1nB;
            s[p][3 * H + lane] = h2nB;
            __syncwarp();

            h2A = h2nA; h2B = h2nB;
        }
    }

    float vA = h2A * W_fc[lane];
    float vB = h2B * W_fc[lane];
    #pragma unroll
    for (int o = 16; o; o >>= 1) {
        vA += __shfl_xor_sync(0xFFFFFFFFu, vA, o);
        vB += __shfl_xor_sync(0xFFFFFFFFu, vB, o);
    }
    if (lane == 0) {
        out[b0] = vA + b_fc[0];
        if (b1 != b0) out[b1] = vB + b_fc[0];
    }
}

extern "C" void kernel_launch(void* const* d_in, const int* in_sizes, int n_in,
                              void* d_out, int out_size)
{
    const float* x     = (const float*)d_in[0];
    const float* W_ih1 = (const float*)d_in[1];
    const float* W_hh1 = (const float*)d_in[2];
    const float* b_ih1 = (const float*)d_in[3];
    const float* b_hh1 = (const float*)d_in[4];
    const float* W_ih2 = (const float*)d_in[5];
    const float* W_hh2 = (const float*)d_in[6];
    const float* b_ih2 = (const float*)d_in[7];
    const float* b_hh2 = (const float*)d_in[8];
    const float* W_fc  = (const float*)d_in[9];
    const float* b_fc  = (const float*)d_in[10];
    float* out = (float*)d_out;

    const int Bn = in_sizes[0] / (T_SEQ * H);

    const int rows = Bn * T_SEQ;
    xin_kernel<<<rows / 256, 128>>>(x, W_ih1, b_ih1, b_hh1);

    rnn_rec_kernel<<<(Bn + 1) / 2, 32>>>(
        W_hh1, W_ih2, W_hh2, b_ih2, b_hh2, W_fc, b_fc, out, Bn);
}

// round 9
// speedup vs baseline: 1.2341x; 1.1007x over previous
#include <cuda_runtime.h>
#include <cstdint>

#define T_SEQ 512
#define H 32
#define MAXB 4096
#define GSTEP 16   // xin tile depth (steps per prefetch group)

typedef unsigned long long u64;

// scratch: xin[b][t][i]; +24 rows pad so tile prefetch may overrun.
__device__ float g_xin[((size_t)MAXB * T_SEQ + 24) * H];

__device__ __forceinline__ u64 fma2(u64 a, u64 b, u64 c) {
    u64 d;
    asm("fma.rn.f32x2 %0, %1, %2, %3;" : "=l"(d) : "l"(a), "l"(b), "l"(c));
    return d;
}
__device__ __forceinline__ u64 add2(u64 a, u64 b) {
    u64 d;
    asm("add.rn.f32x2 %0, %1, %2;" : "=l"(d) : "l"(a), "l"(b));
    return d;
}
__device__ __forceinline__ u64 pack2(float lo, float hi) {
    u64 d;
    asm("mov.b64 %0, {%1, %2};" : "=l"(d) : "f"(lo), "f"(hi));
    return d;
}
__device__ __forceinline__ float lo_hi_sum(u64 a) {
    unsigned lo, hi;
    asm("mov.b64 {%0,%1}, %2;" : "=r"(lo), "=r"(hi) : "l"(a));
    return __uint_as_float(lo) + __uint_as_float(hi);
}
__device__ __forceinline__ float tanh_mufu(float x) {
    float y;
    asm("tanh.approx.f32 %0, %1;" : "=f"(y) : "f"(x));
    return y;
}
__device__ __forceinline__ float tanh_fast(float x) {
    float e = __expf(2.0f * x);
    return 1.0f - __fdividef(2.0f, e + 1.0f);
}

// ============================================================================
// K1: xin precompute (unchanged; ~147us, near DRAM floor).
// ============================================================================
__global__ __launch_bounds__(128)
void xin_kernel(const float* __restrict__ x,
                const float* __restrict__ W_ih1,
                const float* __restrict__ b_ih1,
                const float* __restrict__ b_hh1)
{
    const int tid  = threadIdx.x;
    const int lane = tid & 31;
    const int wid  = tid >> 5;

    __shared__ __align__(16) float sw[32][36];
    __shared__ __align__(16) float sx[4][2][8 * H];

    #pragma unroll
    for (int idx = tid; idx < H * H; idx += 128) sw[idx >> 5][idx & 31] = W_ih1[idx];
    __syncthreads();

    u64 w[16];
    {
        const u64* wr = (const u64*)&sw[lane][0];
        #pragma unroll
        for (int k = 0; k < 16; k++) w[k] = wr[k];
    }
    const u64 biasp = pack2(b_ih1[lane] + b_hh1[lane], 0.0f);

    const long long base = ((long long)blockIdx.x * 4 + wid) * 64;
    const float* xb = x + base * H;
    float* ob = g_xin + base * H;

    float4 p0 = *(const float4*)(xb + lane * 4);
    float4 p1 = *(const float4*)(xb + 128 + lane * 4);

    #pragma unroll
    for (int g = 0; g < 8; g++) {
        const int buf = g & 1;
        *(float4*)&sx[wid][buf][lane * 4]       = p0;
        *(float4*)&sx[wid][buf][128 + lane * 4] = p1;
        if (g < 7) {
            p0 = *(const float4*)(xb + (g + 1) * 256 + lane * 4);
            p1 = *(const float4*)(xb + (g + 1) * 256 + 128 + lane * 4);
        }
        __syncwarp();

        #pragma unroll
        for (int rr = 0; rr < 8; rr += 2) {
            const ulonglong2* xv0 = (const ulonglong2*)&sx[wid][buf][rr * H];
            const ulonglong2* xv1 = (const ulonglong2*)&sx[wid][buf][(rr + 1) * H];
            u64 a0 = biasp, a1 = 0ull, b0 = biasp, b1 = 0ull;
            #pragma unroll
            for (int m = 0; m < 8; m++) {
                ulonglong2 v0 = xv0[m];
                ulonglong2 v1 = xv1[m];
                a0 = fma2(v0.x, w[2 * m],     a0);
                a1 = fma2(v0.y, w[2 * m + 1], a1);
                b0 = fma2(v1.x, w[2 * m],     b0);
                b1 = fma2(v1.y, w[2 * m + 1], b1);
            }
            ob[(g * 8 + rr)     * H + lane] = lo_hi_sum(add2(a0, a1));
            ob[(g * 8 + rr + 1) * H + lane] = lo_hi_sum(add2(b0, b1));
        }
    }
}

// ============================================================================
// K2: layer-pipelined recurrence, ONE batch stream per warp (Q=1), 4096
// single-warp blocks -> ~16 warps/SM (reg-limited), half-j split (S=2),
// GSTEP=16 double-buffered xin tile.
//   h1_{k+1} = tanh(W_hh1 h1_k + xin_{k+1})
//   h2_k     = tanh(W_ih2 h1_k + W_hh2 h2_{k-1} + b2)
// ============================================================================
__global__ __launch_bounds__(32, 16)
void rnn_rec_kernel(const float* __restrict__ W_hh1,
                    const float* __restrict__ W_ih2,
                    const float* __restrict__ W_hh2,
                    const float* __restrict__ b_ih2,
                    const float* __restrict__ b_hh2,
                    const float* __restrict__ W_fc,
                    const float* __restrict__ b_fc,
                    float* __restrict__ out, int Bn)
{
    const int lane = threadIdx.x & 31;
    const int jh   = lane >> 4;        // j-half this lane reads
    const int u0   = lane & 15;        // unit pair (u0, u0+16)
    const int b    = blockIdx.x;
    if (b >= Bn) return;

    __shared__ __align__(16) float s[2][2 * H];     // h ping-pong [buf][h1|h2]
    __shared__ float sx[2][GSTEP][32];              // xin tile [buf][d][lane]

    // per-lane weight half-rows: rows u0, u0+16; cols [16*jh, 16*jh+16)
    u64 w1_0[8], w1_1[8], w2_0[8], w2_1[8], w3_0[8], w3_1[8];
    {
        const int off = jh * 16;
        const u64* p;
        p = (const u64*)(W_hh1 + u0 * H + off);
        #pragma unroll
        for (int k = 0; k < 8; k++) w1_0[k] = p[k];
        p = (const u64*)(W_hh1 + (u0 + 16) * H + off);
        #pragma unroll
        for (int k = 0; k < 8; k++) w1_1[k] = p[k];
        p = (const u64*)(W_ih2 + u0 * H + off);
        #pragma unroll
        for (int k = 0; k < 8; k++) w2_0[k] = p[k];
        p = (const u64*)(W_ih2 + (u0 + 16) * H + off);
        #pragma unroll
        for (int k = 0; k < 8; k++) w2_1[k] = p[k];
        p = (const u64*)(W_hh2 + u0 * H + off);
        #pragma unroll
        for (int k = 0; k < 8; k++) w3_0[k] = p[k];
        p = (const u64*)(W_hh2 + (u0 + 16) * H + off);
        #pragma unroll
        for (int k = 0; k < 8; k++) w3_1[k] = p[k];
    }
    const float bias2 = b_ih2[lane] + b_hh2[lane];  // per-unit (unit == lane)

    const float* xA = g_xin + (size_t)b * T_SEQ * H + lane;

    // prologue: h1_0 = tanh(xin_0), h2_{-1}=0, published to buffer 1
    s[1][lane]     = tanh_fast(xA[0]);
    s[1][H + lane] = 0.0f;
    __syncwarp();

    // preload tile group 0 (steps k=0..15 -> t=1..16)
    #pragma unroll
    for (int d = 0; d < GSTEP; d++)
        sx[0][d][lane] = xA[(size_t)(d + 1) * H];

    float h2A = 0.0f;

    for (int g = 0; g < T_SEQ / GSTEP; ++g) {
        const int buf = g & 1;

        // burst-prefetch next tile (overrun lands in pad, never consumed)
        {
            const size_t tb = (size_t)(g + 1) * GSTEP + 1;
            #pragma unroll
            for (int d = 0; d < GSTEP; d++)
                sx[buf ^ 1][d][lane] = xA[(tb + d) * H];
        }

        #pragma unroll 2
        for (int kk = 0; kk < GSTEP; ++kk) {
            const int p = kk & 1;   // g*16 even -> parity of k == parity of kk
            const float* sq = &s[p ^ 1][jh * 16];
            const ulonglong2* h1v = (const ulonglong2*)(sq);
            const ulonglong2* h2v = (const ulonglong2*)(sq + H);

            const float xinA = sx[buf][kk][lane];   // value for t = k+1

            // acc inits fold xin (layer1, row u0 path) and bias2 (layer2)
            u64 a0 = pack2(xinA, 0.0f), a1 = 0ull;
            u64 c0 = 0ull,              c1 = 0ull;

            #pragma unroll
            for (int m = 0; m < 4; m++) {
                ulonglong2 v = h1v[m];
                a0 = fma2(v.x, w1_0[2 * m],     a0);
                a0 = fma2(v.y, w1_0[2 * m + 1], a0);
                a1 = fma2(v.x, w1_1[2 * m],     a1);
                a1 = fma2(v.y, w1_1[2 * m + 1], a1);
                c0 = fma2(v.x, w2_0[2 * m],     c0);
                c0 = fma2(v.y, w2_0[2 * m + 1], c0);
                c1 = fma2(v.x, w2_1[2 * m],     c1);
                c1 = fma2(v.y, w2_1[2 * m + 1], c1);
            }
            #pragma unroll
            for (int m = 0; m < 4; m++) {
                ulonglong2 v = h2v[m];
                c0 = fma2(v.x, w3_0[2 * m],     c0);
                c0 = fma2(v.y, w3_0[2 * m + 1], c0);
                c1 = fma2(v.x, w3_1[2 * m],     c1);
                c1 = fma2(v.y, w3_1[2 * m + 1], c1);
            }

            float sa0 = lo_hi_sum(a0), sa1 = lo_hi_sum(a1);
            float sc0 = lo_hi_sum(c0), sc1 = lo_hi_sum(c1);

            // combine half-sums with j-partner (lane ^ 16)
            float fa0 = sa0 + __shfl_xor_sync(0xFFFFFFFFu, sa0, 16);
            float fa1 = sa1 + __shfl_xor_sync(0xFFFFFFFFu, sa1, 16);
            float fc0 = sc0 + __shfl_xor_sync(0xFFFFFFFFu, sc0, 16);
            float fc1 = sc1 + __shfl_xor_sync(0xFFFFFFFFu, sc1, 16);

            // xin was folded into a0 (the jh==0 half-sum of row u0 path);
            // for jh==1 lanes the folded xin belongs to row u0 too -- note
            // BOTH halves fold their lane's xin, but xin[lane] differs per
            // lane; after shfl the sum fa0 = (row u0 dot h1) + xin[lane] +
            // xin[lane^16]?  -> WRONG unless only one half folds.
            // To keep it exact we folded xin into a0 for ALL lanes, so
            // subtract the partner's contribution is messy; instead we do
            // NOT rely on the fold across halves: a0's fold is correct only
            // if the partner folded 0.  Handle by folding xin only in jh==0
            // lanes: (done via select below -- see init fix)
            const float h1n = tanh_mufu(jh ? (fa1) : (fa0));
            const float h2n = tanh_mufu((jh ? fc1 : fc0) + bias2);

            s[p][lane]     = h1n;
            s[p][H + lane] = h2n;
            __syncwarp();

            h2A = h2n;
        }
    }

    float v = h2A * W_fc[lane];
    #pragma unroll
    for (int o = 16; o; o >>= 1) v += __shfl_xor_sync(0xFFFFFFFFu, v, o);
    if (lane == 0) out[b] = v + b_fc[0];
}

// NOTE on the xin fold above: lane L folds xin[L] into its a0 chain. After
// shfl_xor(16), fa0(L) = partial_u0(L) + partial_u0(L^16) + xin[L] + xin[L^16].
// That is wrong. FIX: fold xin only where it is consumed. Corrected kernel
// below overrides via macro redefinition is ugly; instead the kernel above is
// NOT used -- the corrected version follows.

__global__ __launch_bounds__(32, 16)
void rnn_rec_kernel_fixed(const float* __restrict__ W_hh1,
                          const float* __restrict__ W_ih2,
                          const float* __restrict__ W_hh2,
                          const float* __restrict__ b_ih2,
                          const float* __restrict__ b_hh2,
                          const float* __restrict__ W_fc,
                          const float* __restrict__ b_fc,
                          float* __restrict__ out, int Bn)
{
    const int lane = threadIdx.x & 31;
    const int jh   = lane >> 4;
    const int u0   = lane & 15;
    const int b    = blockIdx.x;
    if (b >= Bn) return;

    __shared__ __align__(16) float s[2][2 * H];
    __shared__ float sx[2][GSTEP][32];

    u64 w1_0[8], w1_1[8], w2_0[8], w2_1[8], w3_0[8], w3_1[8];
    {
        const int off = jh * 16;
        const u64* p;
        p = (const u64*)(W_hh1 + u0 * H + off);
        #pragma unroll
        for (int k = 0; k < 8; k++) w1_0[k] = p[k];
        p = (const u64*)(W_hh1 + (u0 + 16) * H + off);
        #pragma unroll
        for (int k = 0; k < 8; k++) w1_1[k] = p[k];
        p = (const u64*)(W_ih2 + u0 * H + off);
        #pragma unroll
        for (int k = 0; k < 8; k++) w2_0[k] = p[k];
        p = (const u64*)(W_ih2 + (u0 + 16) * H + off);
        #pragma unroll
        for (int k = 0; k < 8; k++) w2_1[k] = p[k];
        p = (const u64*)(W_hh2 + u0 * H + off);
        #pragma unroll
        for (int k = 0; k < 8; k++) w3_0[k] = p[k];
        p = (const u64*)(W_hh2 + (u0 + 16) * H + off);
        #pragma unroll
        for (int k = 0; k < 8; k++) w3_1[k] = p[k];
    }
    const float bias2 = b_ih2[lane] + b_hh2[lane];

    const float* xA = g_xin + (size_t)b * T_SEQ * H + lane;

    s[1][lane]     = tanh_fast(xA[0]);
    s[1][H + lane] = 0.0f;
    __syncwarp();

    #pragma unroll
    for (int d = 0; d < GSTEP; d++)
        sx[0][d][lane] = xA[(size_t)(d + 1) * H];

    float h2A = 0.0f;

    for (int g = 0; g < T_SEQ / GSTEP; ++g) {
        const int buf = g & 1;
        {
            const size_t tb = (size_t)(g + 1) * GSTEP + 1;
            #pragma unroll
            for (int d = 0; d < GSTEP; d++)
                sx[buf ^ 1][d][lane] = xA[(tb + d) * H];
        }

        #pragma unroll 2
        for (int kk = 0; kk < GSTEP; ++kk) {
            const int p = kk & 1;
            const float* sq = &s[p ^ 1][jh * 16];
            const ulonglong2* h1v = (const ulonglong2*)(sq);
            const ulonglong2* h2v = (const ulonglong2*)(sq + H);

            const float xinA = sx[buf][kk][lane];

            u64 a0 = 0ull, a1 = 0ull, c0 = 0ull, c1 = 0ull;

            #pragma unroll
            for (int m = 0; m < 4; m++) {
                ulonglong2 v = h1v[m];
                a0 = fma2(v.x, w1_0[2 * m],     a0);
                a0 = fma2(v.y, w1_0[2 * m + 1], a0);
                a1 = fma2(v.x, w1_1[2 * m],     a1);
                a1 = fma2(v.y, w1_1[2 * m + 1], a1);
                c0 = fma2(v.x, w2_0[2 * m],     c0);
                c0 = fma2(v.y, w2_0[2 * m + 1], c0);
                c1 = fma2(v.x, w2_1[2 * m],     c1);
                c1 = fma2(v.y, w2_1[2 * m + 1], c1);
            }
            #pragma unroll
            for (int m = 0; m < 4; m++) {
                ulonglong2 v = h2v[m];
                c0 = fma2(v.x, w3_0[2 * m],     c0);
                c0 = fma2(v.y, w3_0[2 * m + 1], c0);
                c1 = fma2(v.x, w3_1[2 * m],     c1);
                c1 = fma2(v.y, w3_1[2 * m + 1], c1);
            }

            float sa0 = lo_hi_sum(a0), sa1 = lo_hi_sum(a1);
            float sc0 = lo_hi_sum(c0), sc1 = lo_hi_sum(c1);

            float fa0 = sa0 + __shfl_xor_sync(0xFFFFFFFFu, sa0, 16);
            float fa1 = sa1 + __shfl_xor_sync(0xFFFFFFFFu, sa1, 16);
            float fc0 = sc0 + __shfl_xor_sync(0xFFFFFFFFu, sc0, 16);
            float fc1 = sc1 + __shfl_xor_sync(0xFFFFFFFFu, sc1, 16);

            const float h1n = tanh_mufu((jh ? fa1 : fa0) + xinA);
            const float h2n = tanh_mufu((jh ? fc1 : fc0) + bias2);

            s[p][lane]     = h1n;
            s[p][H + lane] = h2n;
            __syncwarp();

            h2A = h2n;
        }
    }

    float v = h2A * W_fc[lane];
    #pragma unroll
    for (int o = 16; o; o >>= 1) v += __shfl_xor_sync(0xFFFFFFFFu, v, o);
    if (lane == 0) out[b] = v + b_fc[0];
}

extern "C" void kernel_launch(void* const* d_in, const int* in_sizes, int n_in,
                              void* d_out, int out_size)
{
    const float* x     = (const float*)d_in[0];
    const float* W_ih1 = (const float*)d_in[1];
    const float* W_hh1 = (const float*)d_in[2];
    const float* b_ih1 = (const float*)d_in[3];
    const float* b_hh1 = (const float*)d_in[4];
    const float* W_ih2 = (const float*)d_in[5];
    const float* W_hh2 = (const float*)d_in[6];
    const float* b_ih2 = (const float*)d_in[7];
    const float* b_hh2 = (const float*)d_in[8];
    const float* W_fc  = (const float*)d_in[9];
    const float* b_fc  = (const float*)d_in[10];
    float* out = (float*)d_out;

    const int Bn = in_sizes[0] / (T_SEQ * H);

    const int rows = Bn * T_SEQ;
    xin_kernel<<<rows / 256, 128>>>(x, W_ih1, b_ih1, b_hh1);

    // Q=1: one warp per batch element -> 4096 blocks
    rnn_rec_kernel_fixed<<<Bn, 32>>>(
        W_hh1, W_ih2, W_hh2, b_ih2, b_hh2, W_fc, b_fc, out, Bn);
}